// round 2
// baseline (speedup 1.0000x reference)
#include <cuda_runtime.h>
#include <cstdint>
#include <math.h>

#define N_NODES 100000
#define N_EDGES 6400000
#define BLOCK 256
#define EDGE_GRID 1184   // ~148 SMs * 8 blocks

// ---------------- device scratch (static globals; no runtime allocation) ----
__device__ float4 g_h[N_NODES];      // node features [posx,posy,velx,vely]
__device__ float4 g_y[N_EDGES];      // msg layer-1 pre-BN activations
__device__ float4 g_aggr[N_NODES];   // scatter-add target
__device__ float4 g_t1[N_NODES];     // upd layer-1 pre-BN
__device__ float4 g_t2[N_NODES];     // upd layer-2 pre-BN
// [0..7] msg-BN1 (sum y, sum y^2), [8..15] msg-BN2, [16..23] upd-BN1, [24..31] upd-BN2
__device__ double g_acc[32];

// ---------------- block reduction of 8 float partials into double accumulators
__device__ __forceinline__ void reduce8(float v[8], double* dst) {
    #pragma unroll
    for (int off = 16; off > 0; off >>= 1) {
        #pragma unroll
        for (int k = 0; k < 8; k++)
            v[k] += __shfl_down_sync(0xffffffffu, v[k], off);
    }
    __shared__ float sh[8][BLOCK / 32];
    const int lane = threadIdx.x & 31;
    const int warp = threadIdx.x >> 5;
    const int nwarp = blockDim.x >> 5;
    if (lane == 0) {
        #pragma unroll
        for (int k = 0; k < 8; k++) sh[k][warp] = v[k];
    }
    __syncthreads();
    if (warp == 0) {
        #pragma unroll
        for (int k = 0; k < 8; k++) {
            float x = (lane < nwarp) ? sh[k][lane] : 0.0f;
            #pragma unroll
            for (int off = 16; off > 0; off >>= 1)
                x += __shfl_down_sync(0xffffffffu, x, off);
            if (lane == 0) atomicAdd(&dst[k], (double)x);
        }
    }
}

// ---------------- BN affine param helper: y*scale + shift == batchnorm(y) ----
__device__ __forceinline__ void bn_affine(const double* acc, double cnt,
                                          const float* __restrict__ gamma,
                                          const float* __restrict__ beta,
                                          float sc[4], float sf[4]) {
    #pragma unroll
    for (int k = 0; k < 4; k++) {
        double m = acc[k] / cnt;
        double var = acc[4 + k] / cnt - m * m;
        if (var < 0.0) var = 0.0;
        double r = 1.0 / sqrt(var + 1e-5);
        float g = __ldg(&gamma[k]);
        sc[k] = (float)r * g;
        sf[k] = __ldg(&beta[k]) - (float)(m * r) * g;
    }
}

// ---------------- kernel 0: build node features, zero aggr + accumulators ----
__global__ void k_prep(const float* __restrict__ pos, const float* __restrict__ vel) {
    int n = blockIdx.x * blockDim.x + threadIdx.x;
    if (n < N_NODES) {
        g_h[n] = make_float4(pos[2 * n], pos[2 * n + 1], vel[2 * n], vel[2 * n + 1]);
        g_aggr[n] = make_float4(0.f, 0.f, 0.f, 0.f);
    }
    if (blockIdx.x == 0 && threadIdx.x < 32) g_acc[threadIdx.x] = 0.0;
}

// ---------------- pass A: y = [h_dst, h_src] @ W1 + b1 ; stats --------------
__global__ void k_msg1(const int* __restrict__ ei,
                       const float* __restrict__ W1, const float* __restrict__ b1) {
    float w[8][4], bb[4];
    #pragma unroll
    for (int d = 0; d < 8; d++)
        #pragma unroll
        for (int k = 0; k < 4; k++) w[d][k] = __ldg(&W1[d * 4 + k]);
    #pragma unroll
    for (int k = 0; k < 4; k++) bb[k] = __ldg(&b1[k]);

    float s[8];
    #pragma unroll
    for (int k = 0; k < 8; k++) s[k] = 0.f;

    const int stride = gridDim.x * blockDim.x;
    for (int e = blockIdx.x * blockDim.x + threadIdx.x; e < N_EDGES; e += stride) {
        int src = __ldcs(&ei[e]);
        int dst = __ldcs(&ei[N_EDGES + e]);
        float4 hi = __ldg(&g_h[dst]);   // h_i = h[dst]  (rows 0..3 of W1)
        float4 hj = __ldg(&g_h[src]);   // h_j = h[src]  (rows 4..7 of W1)
        float y[4];
        #pragma unroll
        for (int k = 0; k < 4; k++) {
            float a = bb[k];
            a += hi.x * w[0][k] + hi.y * w[1][k] + hi.z * w[2][k] + hi.w * w[3][k];
            a += hj.x * w[4][k] + hj.y * w[5][k] + hj.z * w[6][k] + hj.w * w[7][k];
            y[k] = a;
            s[k] += a;
            s[4 + k] += a * a;
        }
        __stcs(&g_y[e], make_float4(y[0], y[1], y[2], y[3]));
    }
    reduce8(s, &g_acc[0]);
}

// ---------------- pass B: z = relu(bn1(y)) @ W2 + b2 ; stats ----------------
__global__ void k_msg2(const float* __restrict__ g1, const float* __restrict__ be1,
                       const float* __restrict__ W2, const float* __restrict__ b2) {
    float sc1[4], sf1[4];
    bn_affine(&g_acc[0], (double)N_EDGES, g1, be1, sc1, sf1);
    float w[4][4], bb[4];
    #pragma unroll
    for (int d = 0; d < 4; d++)
        #pragma unroll
        for (int k = 0; k < 4; k++) w[d][k] = __ldg(&W2[d * 4 + k]);
    #pragma unroll
    for (int k = 0; k < 4; k++) bb[k] = __ldg(&b2[k]);

    float s[8];
    #pragma unroll
    for (int k = 0; k < 8; k++) s[k] = 0.f;

    const int stride = gridDim.x * blockDim.x;
    for (int e = blockIdx.x * blockDim.x + threadIdx.x; e < N_EDGES; e += stride) {
        float4 y4 = __ldcs(&g_y[e]);
        float a0 = fmaxf(y4.x * sc1[0] + sf1[0], 0.f);
        float a1 = fmaxf(y4.y * sc1[1] + sf1[1], 0.f);
        float a2 = fmaxf(y4.z * sc1[2] + sf1[2], 0.f);
        float a3 = fmaxf(y4.w * sc1[3] + sf1[3], 0.f);
        #pragma unroll
        for (int k = 0; k < 4; k++) {
            float z = bb[k] + a0 * w[0][k] + a1 * w[1][k] + a2 * w[2][k] + a3 * w[3][k];
            s[k] += z;
            s[4 + k] += z * z;
        }
    }
    reduce8(s, &g_acc[8]);
}

// ---------------- pass C: msg = relu(bn2(z)); scatter-add to aggr[dst] ------
__global__ void k_msg3(const int* __restrict__ ei,
                       const float* __restrict__ g1, const float* __restrict__ be1,
                       const float* __restrict__ W2, const float* __restrict__ b2,
                       const float* __restrict__ g2, const float* __restrict__ be2) {
    float sc1[4], sf1[4], sc2[4], sf2[4];
    bn_affine(&g_acc[0], (double)N_EDGES, g1, be1, sc1, sf1);
    bn_affine(&g_acc[8], (double)N_EDGES, g2, be2, sc2, sf2);
    float w[4][4], bb[4];
    #pragma unroll
    for (int d = 0; d < 4; d++)
        #pragma unroll
        for (int k = 0; k < 4; k++) w[d][k] = __ldg(&W2[d * 4 + k]);
    #pragma unroll
    for (int k = 0; k < 4; k++) bb[k] = __ldg(&b2[k]);

    const int stride = gridDim.x * blockDim.x;
    for (int e = blockIdx.x * blockDim.x + threadIdx.x; e < N_EDGES; e += stride) {
        float4 y4 = __ldcs(&g_y[e]);
        int dst = __ldcs(&ei[N_EDGES + e]);
        float a0 = fmaxf(y4.x * sc1[0] + sf1[0], 0.f);
        float a1 = fmaxf(y4.y * sc1[1] + sf1[1], 0.f);
        float a2 = fmaxf(y4.z * sc1[2] + sf1[2], 0.f);
        float a3 = fmaxf(y4.w * sc1[3] + sf1[3], 0.f);
        float* p = (float*)&g_aggr[dst];
        #pragma unroll
        for (int k = 0; k < 4; k++) {
            float z = bb[k] + a0 * w[0][k] + a1 * w[1][k] + a2 * w[2][k] + a3 * w[3][k];
            float m = fmaxf(z * sc2[k] + sf2[k], 0.f);
            atomicAdd(p + k, m);
        }
    }
}

// ---------------- update MLP pass 1: y1 = [h, aggr] @ W1 + b1 ; stats -------
__global__ void k_upd1(const float* __restrict__ W1, const float* __restrict__ b1) {
    int n = blockIdx.x * blockDim.x + threadIdx.x;
    float s[8];
    #pragma unroll
    for (int k = 0; k < 8; k++) s[k] = 0.f;
    if (n < N_NODES) {
        float4 h = g_h[n];
        float4 ag = g_aggr[n];
        float x[8] = {h.x, h.y, h.z, h.w, ag.x, ag.y, ag.z, ag.w};
        float y[4];
        #pragma unroll
        for (int k = 0; k < 4; k++) {
            float a = __ldg(&b1[k]);
            #pragma unroll
            for (int d = 0; d < 8; d++) a += x[d] * __ldg(&W1[d * 4 + k]);
            y[k] = a;
            s[k] = a;
            s[4 + k] = a * a;
        }
        g_t1[n] = make_float4(y[0], y[1], y[2], y[3]);
    }
    reduce8(s, &g_acc[16]);
}

// ---------------- update MLP pass 2: z = relu(bn(y1)) @ W2 + b2 ; stats -----
__global__ void k_upd2(const float* __restrict__ g1, const float* __restrict__ be1,
                       const float* __restrict__ W2, const float* __restrict__ b2) {
    float sc[4], sf[4];
    bn_affine(&g_acc[16], (double)N_NODES, g1, be1, sc, sf);
    int n = blockIdx.x * blockDim.x + threadIdx.x;
    float s[8];
    #pragma unroll
    for (int k = 0; k < 8; k++) s[k] = 0.f;
    if (n < N_NODES) {
        float4 y4 = g_t1[n];
        float a0 = fmaxf(y4.x * sc[0] + sf[0], 0.f);
        float a1 = fmaxf(y4.y * sc[1] + sf[1], 0.f);
        float a2 = fmaxf(y4.z * sc[2] + sf[2], 0.f);
        float a3 = fmaxf(y4.w * sc[3] + sf[3], 0.f);
        float z[4];
        #pragma unroll
        for (int k = 0; k < 4; k++) {
            float v = __ldg(&b2[k]);
            v += a0 * __ldg(&W2[0 * 4 + k]) + a1 * __ldg(&W2[1 * 4 + k])
               + a2 * __ldg(&W2[2 * 4 + k]) + a3 * __ldg(&W2[3 * 4 + k]);
            z[k] = v;
            s[k] = v;
            s[4 + k] = v * v;
        }
        g_t2[n] = make_float4(z[0], z[1], z[2], z[3]);
    }
    reduce8(s, &g_acc[24]);
}

// ---------------- output head: out = relu(bn(z)) @ predW + predb ------------
__global__ void k_out(const float* __restrict__ g2, const float* __restrict__ be2,
                      const float* __restrict__ PW, const float* __restrict__ pb,
                      float* __restrict__ out) {
    float sc[4], sf[4];
    bn_affine(&g_acc[24], (double)N_NODES, g2, be2, sc, sf);
    int n = blockIdx.x * blockDim.x + threadIdx.x;
    if (n >= N_NODES) return;
    float4 z4 = g_t2[n];
    float o0 = fmaxf(z4.x * sc[0] + sf[0], 0.f);
    float o1 = fmaxf(z4.y * sc[1] + sf[1], 0.f);
    float o2 = fmaxf(z4.z * sc[2] + sf[2], 0.f);
    float o3 = fmaxf(z4.w * sc[3] + sf[3], 0.f);
    // pred_W is [4,2] row-major
    out[2 * n + 0] = __ldg(&pb[0]) + o0 * __ldg(&PW[0]) + o1 * __ldg(&PW[2])
                   + o2 * __ldg(&PW[4]) + o3 * __ldg(&PW[6]);
    out[2 * n + 1] = __ldg(&pb[1]) + o0 * __ldg(&PW[1]) + o1 * __ldg(&PW[3])
                   + o2 * __ldg(&PW[5]) + o3 * __ldg(&PW[7]);
}

extern "C" void kernel_launch(void* const* d_in, const int* in_sizes, int n_in,
                              void* d_out, int out_size) {
    const float* pos    = (const float*)d_in[0];
    const float* vel    = (const float*)d_in[1];
    const int*   ei     = (const int*)d_in[2];     // int32 (JAX x64 disabled)
    const float* msgW1  = (const float*)d_in[3];
    const float* msgb1  = (const float*)d_in[4];
    const float* msgg1  = (const float*)d_in[5];
    const float* msgbe1 = (const float*)d_in[6];
    const float* msgW2  = (const float*)d_in[7];
    const float* msgb2  = (const float*)d_in[8];
    const float* msgg2  = (const float*)d_in[9];
    const float* msgbe2 = (const float*)d_in[10];
    const float* updW1  = (const float*)d_in[11];
    const float* updb1  = (const float*)d_in[12];
    const float* updg1  = (const float*)d_in[13];
    const float* updbe1 = (const float*)d_in[14];
    const float* updW2  = (const float*)d_in[15];
    const float* updb2  = (const float*)d_in[16];
    const float* updg2  = (const float*)d_in[17];
    const float* updbe2 = (const float*)d_in[18];
    const float* predW  = (const float*)d_in[19];
    const float* predb  = (const float*)d_in[20];
    float* out = (float*)d_out;

    const int node_blocks = (N_NODES + BLOCK - 1) / BLOCK;

    k_prep<<<node_blocks, BLOCK>>>(pos, vel);
    k_msg1<<<EDGE_GRID, BLOCK>>>(ei, msgW1, msgb1);
    k_msg2<<<EDGE_GRID, BLOCK>>>(msgg1, msgbe1, msgW2, msgb2);
    k_msg3<<<EDGE_GRID, BLOCK>>>(ei, msgg1, msgbe1, msgW2, msgb2, msgg2, msgbe2);
    k_upd1<<<node_blocks, BLOCK>>>(updW1, updb1);
    k_upd2<<<node_blocks, BLOCK>>>(updg1, updbe1, updW2, updb2);
    k_out<<<node_blocks, BLOCK>>>(updg2, updbe2, predW, predb, out);
}